// round 14
// baseline (speedup 1.0000x reference)
#include <cuda_runtime.h>
#include <cuda_fp16.h>

#define DEGREE 20
#define NINT   2048                 // quadratic intervals over [-1, 1]
#define SCALEF 1024.0f              // xi = (x+1)*1024 in [0, 2048]
#define NBUILD 8                    // producer blocks (NINT / 256)

// R13: fused table kernel 16.9us; L1(crossbar)=55% is the wall, fma idle.
// R14: hybrid warp specialization — per block, warps 0-3 run the smem-table
//   path (crossbar-bound) on the first 55% of elements, warps 4-7 run exact
//   Clenshaw (fma-bound) on the rest. Disjoint bottlenecks overlap; both
//   paths individually validated (R4 / R13). 5 blocks/SM (regs ~50).

__device__ float2 g_tab[NINT];      // static scratch (no allocation)
__device__ int    g_done;           // zero-init; monotonic across replays

// ---- exact Clenshaw (register coefficients, hot path for warps 4-7) ----
__device__ __forceinline__ float legendre_eval(float xx, const float* __restrict__ cp) {
    float d1 = 0.0f, d2 = 0.0f;
#pragma unroll
    for (int k = DEGREE; k >= 0; --k) {
        float g = -(float)((k + 1) * (k + 1)) / (float)((2 * k + 1) * (2 * k + 3));
        float u = fmaf(g, d2, cp[k]);   // FFMA-imm
        float d0 = fmaf(xx, d1, u);     // FFMA 3-reg
        d2 = d1;
        d1 = d0;
    }
    return d1 * fmaf(-xx, xx, 1.0f);    // * (1 - x^2)
}

// ---- exact Clenshaw with shared-memory coefficients (cold build path) ----
__device__ __forceinline__ float legendre_eval_sh(float xx, const float* cp) {
    float d1 = 0.0f, d2 = 0.0f;
#pragma unroll
    for (int k = DEGREE; k >= 0; --k) {
        float g = -(float)((k + 1) * (k + 1)) / (float)((2 * k + 1) * (2 * k + 3));
        float u = fmaf(g, d2, cp[k]);
        float d0 = fmaf(xx, d1, u);
        d2 = d1;
        d1 = d0;
    }
    return d1 * fmaf(-xx, xx, 1.0f);
}

__device__ __forceinline__ float node_x(int i, int j) {
    return (float)(2 * i + j) * (1.0f / 2048.0f) - 1.0f;   // exact dyadic
}

__device__ __forceinline__ float2 make_entry(int i, const float* cp) {
    float f0 = legendre_eval_sh(node_x(i, 0), cp);
    float fh = legendre_eval_sh(node_x(i, 1), cp);
    float f1 = legendre_eval_sh(node_x(i, 2), cp);
    float b1 = 4.0f * fh - 3.0f * f0 - f1;   // p(t) = f0 + t*(b1 + b2*t)
    float b2 = 2.0f * (f0 + f1) - 4.0f * fh;
    __half2 h2 = __floats2half2_rn(b1, b2);
    float2 e;
    e.x = f0;
    e.y = __uint_as_float(*reinterpret_cast<unsigned int*>(&h2));
    return e;
}

__device__ __forceinline__ void fill_cp(float* cp, const float* __restrict__ W) {
    float M = 1.0f;
    cp[0] = __ldg(&W[0]);
#pragma unroll
    for (int k = 1; k <= DEGREE; ++k) {
        M *= (float)(2 * k - 1) / (float)k;   // ratio folds to immediate
        cp[k] = __ldg(&W[k]) * M;
    }
}

__device__ __forceinline__ float interp1(float xx, const float2* tab) {
    float xi = fmaf(xx, SCALEF, SCALEF);       // >= 0 for x >= -1
    float fl = floorf(xi);
    fl = fminf(fl, (float)(NINT - 1));
    float t = xi - fl;                         // t in [0, 1]
    int idx = (int)fl;
    float2 c = tab[idx];
    unsigned int u = __float_as_uint(c.y);
    __half2 h2 = *reinterpret_cast<__half2*>(&u);
    float2 a = __half22float2(h2);
    return fmaf(t, fmaf(t, a.y, a.x), c.x);
}

__global__ __launch_bounds__(256, 5) void legendre_hybrid_kernel(
    const float* __restrict__ x, const float* __restrict__ W,
    float* __restrict__ out, int n)
{
    __shared__ float2 tab[NINT];               // 16 KB
    __shared__ float  cp_sh[DEGREE + 1];
    __shared__ int    s_ready;

    const int tid = threadIdx.x;

    // ---- producers: blocks 0..7 build the global table (R13, validated) ----
    if (blockIdx.x < NBUILD) {
        if (tid == 0) fill_cp(cp_sh, W);
        __syncthreads();
        int i = blockIdx.x * 256 + tid;
        g_tab[i] = make_entry(i, cp_sh);
        __threadfence();
        __syncthreads();
        if (tid == 0) atomicAdd(&g_done, 1);
    }

    // ---- wait for table (bounded spin; fallback = local rebuild) ----
    if (tid == 0) {
        int spins = 0;
        while (*(volatile int*)&g_done < NBUILD && spins < 4000000) ++spins;
        s_ready = (*(volatile int*)&g_done >= NBUILD) ? 1 : 0;
    }
    __syncthreads();

    if (s_ready) {
        __threadfence();
        const float4* src = (const float4*)g_tab;
        float4* dst = (float4*)tab;
        for (int k = tid; k < NINT / 2; k += 256)
            dst[k] = src[k];
    } else {
        if (tid == 0) fill_cp(cp_sh, W);
        __syncthreads();
        for (int e = tid; e < NINT; e += 256)
            tab[e] = make_entry(e, cp_sh);
    }
    __syncthreads();

    // ---- warp-specialized main loop ----
    const int n4 = n >> 2;
    const int n4t = (int)(((long long)n4 * 11) / 20);   // 55% -> table path
    const int half_stride = gridDim.x * 128;            // 128 threads/path/block

    const float4* __restrict__ x4 = (const float4*)x;
    float4* __restrict__ o4 = (float4*)out;

    if (tid < 128) {
        // ---- table path: elements [0, n4t), crossbar-bound ----
        int i = blockIdx.x * 128 + tid;
        if (i < n4t) {
            float4 v = x4[i];
            for (; i + half_stride < n4t; i += half_stride) {
                float4 vn = x4[i + half_stride];       // depth-1 prefetch
                float4 r;
                r.x = interp1(v.x, tab);
                r.y = interp1(v.y, tab);
                r.z = interp1(v.z, tab);
                r.w = interp1(v.w, tab);
                o4[i] = r;
                v = vn;
            }
            float4 r;
            r.x = interp1(v.x, tab);
            r.y = interp1(v.y, tab);
            r.z = interp1(v.z, tab);
            r.w = interp1(v.w, tab);
            o4[i] = r;
        }
        // Scalar tail (n % 4 != 0) — empty for n = 8,000,000.
        for (int j = (n4 << 2) + blockIdx.x * 128 + tid; j < n; j += half_stride)
            out[j] = interp1(x[j], tab);
    } else {
        // ---- direct path: elements [n4t, n4), fma-bound (exact) ----
        float cp[DEGREE + 1];
        fill_cp(cp, W);
        int i = n4t + blockIdx.x * 128 + (tid - 128);
        if (i < n4) {
            float4 v = x4[i];
            for (; i + half_stride < n4; i += half_stride) {
                float4 vn = x4[i + half_stride];       // depth-1 prefetch
                float4 r;
                r.x = legendre_eval(v.x, cp);
                r.y = legendre_eval(v.y, cp);
                r.z = legendre_eval(v.z, cp);
                r.w = legendre_eval(v.w, cp);
                o4[i] = r;
                v = vn;
            }
            float4 r;
            r.x = legendre_eval(v.x, cp);
            r.y = legendre_eval(v.y, cp);
            r.z = legendre_eval(v.z, cp);
            r.w = legendre_eval(v.w, cp);
            o4[i] = r;
        }
    }
}

extern "C" void kernel_launch(void* const* d_in, const int* in_sizes, int n_in,
                              void* d_out, int out_size) {
    // Identify W by its element count (DEGREE+1); x is the big array.
    const float* x = (const float*)d_in[0];
    const float* W = (const float*)d_in[1];
    if (n_in >= 2 && in_sizes[0] == DEGREE + 1 && in_sizes[1] != DEGREE + 1) {
        x = (const float*)d_in[1];
        W = (const float*)d_in[0];
    }
    float* out = (float*)d_out;
    int n = out_size;

    // 740 = exactly 5 blocks/SM on 148 SMs (51-reg budget for the direct
    // warps, 16KB smem). Single fused launch.
    legendre_hybrid_kernel<<<740, 256>>>(x, W, out, n);
}